// round 6
// baseline (speedup 1.0000x reference)
#include <cuda_runtime.h>
#include <math.h>
#include <cstdint>

#define NPART 32768
#define DD 32
#define PP 8
#define HH 128
#define MS 50
#define TPB 128
#define NBLK 148
#define SLOTS (TPB * NBLK)   // 18944 threads; 2 particle slots each

typedef unsigned long long u64;

// ---- packed f32x2 helpers (sm_103a) ----
__device__ __forceinline__ u64 pack2(float lo, float hi) {
    u64 r; asm("mov.b64 %0, {%1, %2};" : "=l"(r) : "f"(lo), "f"(hi)); return r;
}
__device__ __forceinline__ void unpack2(u64 v, float& lo, float& hi) {
    asm("mov.b64 {%0, %1}, %2;" : "=f"(lo), "=f"(hi) : "l"(v));
}
__device__ __forceinline__ u64 fma2(u64 a, u64 b, u64 c) {
    u64 d; asm("fma.rn.f32x2 %0, %1, %2, %3;" : "=l"(d) : "l"(a), "l"(b), "l"(c)); return d;
}
__device__ __forceinline__ u64 add2(u64 a, u64 b) {
    u64 d; asm("add.rn.f32x2 %0, %1, %2;" : "=l"(d) : "l"(a), "l"(b)); return d;
}
__device__ __forceinline__ u64 mul2(u64 a, u64 b) {
    u64 d; asm("mul.rn.f32x2 %0, %1, %2;" : "=l"(d) : "l"(a), "l"(b)); return d;
}
__device__ __forceinline__ uint32_t smem_u32(const void* p) {
    uint32_t a;
    asm("{ .reg .u64 t; cvta.to.shared.u64 t, %1; cvt.u32.u64 %0, t; }"
        : "=r"(a) : "l"(p));
    return a;
}
__device__ __forceinline__ float ftanh(float a) {
    float e = __expf(2.0f * a);
    return 1.0f - __fdividef(2.0f, e + 1.0f);
}
#define CP16(dst, src) \
    asm volatile("cp.async.cg.shared.global [%0], [%1], 16;" \
                 :: "r"(dst), "l"(src) : "memory")

// shared layout (float offsets)
#define F_W1T 0                      // [j][i] 128x32
#define F_W2S (F_W1T + HH * DD)      // [j][k] 128x32
#define F_CB  (F_W2S + HH * DD)      // float2[128]
#define F_B2  (F_CB + 2 * HH)        // 32
#define F_NA  (F_B2 + DD)            // noise staging A: [chunk(8)][tid(128)][4]
#define F_NB  (F_NA + TPB * DD)
#define SMEM_FLOATS (F_NB + TPB * DD)
#define SMEM_BYTES (SMEM_FLOATS * 4)

__global__ __launch_bounds__(TPB, 1)
void sde_kernel(const float* __restrict__ obs,
                const float* __restrict__ X0,
                const float* __restrict__ V0,
                const float* __restrict__ noise,
                const float* __restrict__ W1,
                const float* __restrict__ b1,
                const float* __restrict__ W2,
                const float* __restrict__ b2,
                const float* __restrict__ theta_p,
                const int*   __restrict__ obsidx_p,
                const int*   __restrict__ cr_p,
                float* __restrict__ outX,
                float* __restrict__ outV)
{
    extern __shared__ __align__(16) float sm[];
    float*  W1T = sm + F_W1T;
    float*  W2s = sm + F_W2S;
    float2* cb  = (float2*)(sm + F_CB);
    float*  b2s = sm + F_B2;
    float*  nsA = sm + F_NA;
    float*  nsB = sm + F_NB;

    const int tid = threadIdx.x;

    // ---- stage weights ----
    for (int idx = tid; idx < DD * HH; idx += TPB) {
        int i = idx >> 7;            // feature
        int j = idx & (HH - 1);      // hidden unit
        W1T[j * DD + i] = W1[idx];
    }
    for (int idx = tid; idx < HH * DD; idx += TPB)
        W2s[idx] = W2[idx];          // already [j][k]
    if (tid < DD) b2s[tid] = b2[tid];
    {
        const int j = tid;           // TPB == HH
        float base = b1[j];
        #pragma unroll
        for (int q = 0; q < PP; q++)
            base = fmaf(obs[q], W1[(DD + q) * HH + j], base);
        base = fmaf((float)(*obsidx_p), W1[41 * HH + j], base);
        cb[j] = make_float2(base, W1[40 * HH + j]);
    }

    const float theta = *theta_p;
    const float crf   = (float)(*cr_p);
    const float dt    = 0.02f;
    const float sqdt  = sqrtf(dt);

    const u64 sq2   = pack2(sqdt, sqdt);
    const u64 dt2   = pack2(dt, dt);
    const u64 nth2  = pack2(-theta, -theta);
    const u64 ncr2  = pack2(-crf, -crf);
    const u64 zero2 = pack2(0.f, 0.f);

    const int gtid = (int)blockIdx.x * TPB + tid;
    const int pA  = gtid;
    const int pB  = gtid + SLOTS;
    const int pBc = (pB < NPART) ? pB : (NPART - 1);   // clamp for loads

    const uint32_t nsAu = smem_u32(nsA) + (uint32_t)tid * 16u;
    const uint32_t nsBu = smem_u32(nsB) + (uint32_t)tid * 16u;
    const float* nArd = nsA + tid * 4;
    const float* nBrd = nsB + tid * 4;

    __syncthreads();

    // ---- state (2 particles) packed f32x2 ----
    u64 XA[DD/2], XB[DD/2], ZA[DD/2], ZB[DD/2];
    {
        const ulonglong2* xa = (const ulonglong2*)(X0 + (size_t)pA * DD);
        const ulonglong2* xb = (const ulonglong2*)(X0 + (size_t)pBc * DD);
        #pragma unroll
        for (int i = 0; i < DD/4; i++) {
            ulonglong2 va = xa[i]; XA[2*i] = va.x; XA[2*i+1] = va.y;
            ulonglong2 vb = xb[i]; XB[2*i] = vb.x; XB[2*i+1] = vb.y;
        }
    }
    float VA = V0[pA];
    float VB = V0[pBc];

    const u64* b2u = (const u64*)b2s;

    for (int m = 0; m < MS; m++) {
        const float s = (float)m * dt;

        // stage this step's noise rows into shared (consumed at epilogue)
        {
            const float* srcA = noise + ((size_t)m * NPART + pA) * DD;
            const float* srcB = noise + ((size_t)m * NPART + pBc) * DD;
            #pragma unroll
            for (int i = 0; i < 8; i++) {
                CP16(nsAu + (uint32_t)i * (TPB * 16u), srcA + i * 4);
                CP16(nsBu + (uint32_t)i * (TPB * 16u), srcB + i * 4);
            }
            asm volatile("cp.async.commit_group;" ::: "memory");
        }

        #pragma unroll
        for (int i = 0; i < DD/2; i++) { u64 b = b2u[i]; ZA[i] = b; ZB[i] = b; }

        // two hidden units per iteration (j and j+64): 4 tanh chains in flight
        for (int jj = 0; jj < HH / 2; jj++) {
            const int j0 = jj, j1 = jj + HH / 2;
            const ulonglong2* w1a = (const ulonglong2*)(W1T + j0 * DD);
            const ulonglong2* w1b = (const ulonglong2*)(W1T + j1 * DD);

            u64 aA0 = zero2, aA1 = zero2, aB0 = zero2, aB1 = zero2;  // j0
            u64 cA0 = zero2, cA1 = zero2, cB0 = zero2, cB1 = zero2;  // j1
            #pragma unroll
            for (int i = 0; i < 8; i++) {
                ulonglong2 wa = w1a[i];
                ulonglong2 wb = w1b[i];
                aA0 = fma2(XA[2*i],   wa.x, aA0);
                aA1 = fma2(XA[2*i+1], wa.y, aA1);
                aB0 = fma2(XB[2*i],   wa.x, aB0);
                aB1 = fma2(XB[2*i+1], wa.y, aB1);
                cA0 = fma2(XA[2*i],   wb.x, cA0);
                cA1 = fma2(XA[2*i+1], wb.y, cA1);
                cB0 = fma2(XB[2*i],   wb.x, cB0);
                cB1 = fma2(XB[2*i+1], wb.y, cB1);
            }
            aA0 = add2(aA0, aA1);
            aB0 = add2(aB0, aB1);
            cA0 = add2(cA0, cA1);
            cB0 = add2(cB0, cB1);

            const float2 c0 = cb[j0];
            const float2 c1 = cb[j1];
            const float cs0 = fmaf(s, c0.y, c0.x);
            const float cs1 = fmaf(s, c1.y, c1.x);

            float t0, t1;
            unpack2(aA0, t0, t1); const float pA0 = cs0 + (t0 + t1);
            unpack2(aB0, t0, t1); const float pB0 = cs0 + (t0 + t1);
            unpack2(cA0, t0, t1); const float pA1 = cs1 + (t0 + t1);
            unpack2(cB0, t0, t1); const float pB1 = cs1 + (t0 + t1);

            // 4 independent tanh chains — MUFU latency overlaps across them
            const float hA0 = ftanh(pA0);
            const float hB0 = ftanh(pB0);
            const float hA1 = ftanh(pA1);
            const float hB1 = ftanh(pB1);
            const u64 hA0p = pack2(hA0, hA0);
            const u64 hB0p = pack2(hB0, hB0);
            const u64 hA1p = pack2(hA1, hA1);
            const u64 hB1p = pack2(hB1, hB1);

            const ulonglong2* w2a = (const ulonglong2*)(W2s + j0 * DD);
            const ulonglong2* w2b = (const ulonglong2*)(W2s + j1 * DD);
            #pragma unroll
            for (int i = 0; i < 8; i++) {
                ulonglong2 wa = w2a[i];
                ulonglong2 wb = w2b[i];
                ZA[2*i]   = fma2(hA0p, wa.x, ZA[2*i]);
                ZA[2*i+1] = fma2(hA0p, wa.y, ZA[2*i+1]);
                ZB[2*i]   = fma2(hB0p, wa.x, ZB[2*i]);
                ZB[2*i+1] = fma2(hB0p, wa.y, ZB[2*i+1]);
                ZA[2*i]   = fma2(hA1p, wb.x, ZA[2*i]);
                ZA[2*i+1] = fma2(hA1p, wb.y, ZA[2*i+1]);
                ZB[2*i]   = fma2(hB1p, wb.x, ZB[2*i]);
                ZB[2*i+1] = fma2(hB1p, wb.y, ZB[2*i+1]);
            }
        }

        // ---- epilogue (noise from shared; per particle) ----
        asm volatile("cp.async.wait_group 0;" ::: "memory");

        #pragma unroll
        for (int pp = 0; pp < 2; pp++) {
            u64* Zp = pp ? ZB : ZA;
            u64* Xp = pp ? XB : XA;
            const float* nrd = pp ? nBrd : nArd;
            float& V = pp ? VB : VA;

            u64 s20 = zero2, s21 = zero2, s22 = zero2, s23 = zero2;
            u64 zw0 = zero2, zw1 = zero2, zw2 = zero2, zw3 = zero2;
            #pragma unroll
            for (int i = 0; i < 4; i++) {
                ulonglong2 nv0 = *(const ulonglong2*)(nrd + (2*i)     * (TPB * 4));
                ulonglong2 nv1 = *(const ulonglong2*)(nrd + (2*i + 1) * (TPB * 4));
                u64 za = Zp[4*i],     zb = Zp[4*i + 1];
                u64 zc = Zp[4*i + 2], zd = Zp[4*i + 3];
                s20 = fma2(za, za, s20);
                s21 = fma2(zb, zb, s21);
                s22 = fma2(zc, zc, s22);
                s23 = fma2(zd, zd, s23);
                u64 wa = mul2(sq2, nv0.x);
                u64 wb = mul2(sq2, nv0.y);
                u64 wc = mul2(sq2, nv1.x);
                u64 wd = mul2(sq2, nv1.y);
                zw0 = fma2(za, wa, zw0);
                zw1 = fma2(zb, wb, zw1);
                zw2 = fma2(zc, wc, zw2);
                zw3 = fma2(zd, wd, zw3);
                u64 d0 = fma2(ncr2, za, mul2(nth2, Xp[4*i]));
                u64 d1 = fma2(ncr2, zb, mul2(nth2, Xp[4*i + 1]));
                u64 d2 = fma2(ncr2, zc, mul2(nth2, Xp[4*i + 2]));
                u64 d3 = fma2(ncr2, zd, mul2(nth2, Xp[4*i + 3]));
                Xp[4*i]     = add2(fma2(dt2, d0, Xp[4*i]),     wa);
                Xp[4*i + 1] = add2(fma2(dt2, d1, Xp[4*i + 1]), wb);
                Xp[4*i + 2] = add2(fma2(dt2, d2, Xp[4*i + 2]), wc);
                Xp[4*i + 3] = add2(fma2(dt2, d3, Xp[4*i + 3]), wd);
            }
            s20 = add2(add2(s20, s21), add2(s22, s23));
            zw0 = add2(add2(zw0, zw1), add2(zw2, zw3));
            float qlo, qhi, wlo, whi;
            unpack2(s20, qlo, qhi);
            unpack2(zw0, wlo, whi);
            V = fmaf(dt * (0.5f - crf), qlo + qhi, V) + (wlo + whi);
        }
    }

    // ---- store ----
    {
        ulonglong2* xa = (ulonglong2*)(outX + (size_t)pA * DD);
        #pragma unroll
        for (int i = 0; i < DD/4; i++) {
            ulonglong2 va; va.x = XA[2*i]; va.y = XA[2*i+1]; xa[i] = va;
        }
        outV[pA] = VA;
        if (pB < NPART) {
            ulonglong2* xb = (ulonglong2*)(outX + (size_t)pB * DD);
            #pragma unroll
            for (int i = 0; i < DD/4; i++) {
                ulonglong2 vb; vb.x = XB[2*i]; vb.y = XB[2*i+1]; xb[i] = vb;
            }
            outV[pB] = VB;
        }
    }
}

extern "C" void kernel_launch(void* const* d_in, const int* in_sizes, int n_in,
                              void* d_out, int out_size) {
    const float* obs    = (const float*)d_in[0];
    const float* X0     = (const float*)d_in[1];
    const float* V0     = (const float*)d_in[2];
    const float* noise  = (const float*)d_in[3];
    const float* W1     = (const float*)d_in[4];
    const float* b1     = (const float*)d_in[5];
    const float* W2     = (const float*)d_in[6];
    const float* b2     = (const float*)d_in[7];
    const float* theta  = (const float*)d_in[8];
    const int*   obsidx = (const int*)d_in[9];
    const int*   cr     = (const int*)d_in[10];

    float* out  = (float*)d_out;
    float* outX = out;
    float* outV = out + (size_t)NPART * DD;

    cudaFuncSetAttribute(sde_kernel,
                         cudaFuncAttributeMaxDynamicSharedMemorySize, SMEM_BYTES);
    sde_kernel<<<NBLK, TPB, SMEM_BYTES>>>(obs, X0, V0, noise, W1, b1, W2, b2,
                                          theta, obsidx, cr, outX, outV);
}

// round 8
// speedup vs baseline: 1.1238x; 1.1238x over previous
#include <cuda_runtime.h>
#include <math.h>
#include <cstdint>

#define NPART 32768
#define DD 32
#define PP 8
#define HH 128
#define MS 50
#define TPB 256
#define NBLK 128   // TPB*NBLK == NPART exactly

typedef unsigned long long u64;

// W2 weights, j-major [128][32] — straight copy from input, read over the
// constant port (uniform per-warp index) instead of the smem crossbar.
__constant__ float W2c[HH * DD];

// ---- packed f32x2 helpers (sm_103a) ----
__device__ __forceinline__ u64 pack2(float lo, float hi) {
    u64 r; asm("mov.b64 %0, {%1, %2};" : "=l"(r) : "f"(lo), "f"(hi)); return r;
}
__device__ __forceinline__ void unpack2(u64 v, float& lo, float& hi) {
    asm("mov.b64 {%0, %1}, %2;" : "=f"(lo), "=f"(hi) : "l"(v));
}
__device__ __forceinline__ u64 fma2(u64 a, u64 b, u64 c) {
    u64 d; asm("fma.rn.f32x2 %0, %1, %2, %3;" : "=l"(d) : "l"(a), "l"(b), "l"(c)); return d;
}
__device__ __forceinline__ u64 add2(u64 a, u64 b) {
    u64 d; asm("add.rn.f32x2 %0, %1, %2;" : "=l"(d) : "l"(a), "l"(b)); return d;
}
__device__ __forceinline__ u64 mul2(u64 a, u64 b) {
    u64 d; asm("mul.rn.f32x2 %0, %1, %2;" : "=l"(d) : "l"(a), "l"(b)); return d;
}
__device__ __forceinline__ uint32_t smem_u32(const void* p) {
    uint32_t a;
    asm("{ .reg .u64 t; cvta.to.shared.u64 t, %1; cvt.u32.u64 %0, t; }"
        : "=r"(a) : "l"(p));
    return a;
}
__device__ __forceinline__ float ftanh(float a) {
    float e = __expf(2.0f * a);
    return 1.0f - __fdividef(2.0f, e + 1.0f);
}
#define CP16(dst, src) \
    asm volatile("cp.async.cg.shared.global [%0], [%1], 16;" \
                 :: "r"(dst), "l"(src) : "memory")

// shared layout (float offsets)
#define F_W1T 0                      // [j][i] 128x32
#define F_CB  (F_W1T + HH * DD)      // float2[128]
#define F_B2  (F_CB + 2 * HH)        // 32
#define F_NS  (F_B2 + DD)            // noise staging: [chunk(8)][tid(256)][4]
#define SMEM_FLOATS (F_NS + TPB * DD)
#define SMEM_BYTES (SMEM_FLOATS * 4)

__global__ __launch_bounds__(TPB, 1)
void sde_kernel(const float* __restrict__ obs,
                const float* __restrict__ X0,
                const float* __restrict__ V0,
                const float* __restrict__ noise,
                const float* __restrict__ W1,
                const float* __restrict__ b1,
                const float* __restrict__ b2,
                const float* __restrict__ theta_p,
                const int*   __restrict__ obsidx_p,
                const int*   __restrict__ cr_p,
                float* __restrict__ outX,
                float* __restrict__ outV)
{
    extern __shared__ __align__(16) float sm[];
    float*  W1T = sm + F_W1T;
    float2* cb  = (float2*)(sm + F_CB);
    float*  b2s = sm + F_B2;
    float*  ns  = sm + F_NS;

    const int tid = threadIdx.x;

    // ---- stage W1^T + folded constants ----
    for (int idx = tid; idx < DD * HH; idx += TPB) {
        int i = idx >> 7;            // feature
        int j = idx & (HH - 1);      // hidden unit
        W1T[j * DD + i] = W1[idx];
    }
    if (tid < DD) b2s[tid] = b2[tid];
    if (tid < HH) {
        const int j = tid;
        float base = b1[j];
        #pragma unroll
        for (int q = 0; q < PP; q++)
            base = fmaf(obs[q], W1[(DD + q) * HH + j], base);
        base = fmaf((float)(*obsidx_p), W1[41 * HH + j], base);
        cb[j] = make_float2(base, W1[40 * HH + j]);
    }

    const float theta = *theta_p;
    const float crf   = (float)(*cr_p);
    const float dt    = 0.02f;
    const float sqdt  = sqrtf(dt);

    const u64 sq2   = pack2(sqdt, sqdt);
    const u64 dt2   = pack2(dt, dt);
    const u64 nth2  = pack2(-theta, -theta);
    const u64 ncr2  = pack2(-crf, -crf);
    const u64 zero2 = pack2(0.f, 0.f);

    const int p = (int)blockIdx.x * TPB + tid;   // exactly NPART threads

    const uint32_t nsu = smem_u32(ns) + (uint32_t)tid * 16u;
    const float* nrd = ns + tid * 4;

    __syncthreads();

    // ---- state (1 particle) packed f32x2: X 16 u64, Z 16 u64 ----
    u64 Xp[DD/2], Zp[DD/2];
    {
        const ulonglong2* xr = (const ulonglong2*)(X0 + (size_t)p * DD);
        #pragma unroll
        for (int i = 0; i < DD/4; i++) {
            ulonglong2 v = xr[i];
            Xp[2*i] = v.x; Xp[2*i+1] = v.y;
        }
    }
    float V = V0[p];

    const u64* b2u = (const u64*)b2s;

    for (int m = 0; m < MS; m++) {
        const float s = (float)m * dt;

        // stage this step's noise row into shared (epilogue consumes)
        {
            const float* src = noise + ((size_t)m * NPART + p) * DD;
            #pragma unroll
            for (int i = 0; i < 8; i++)
                CP16(nsu + (uint32_t)i * (TPB * 16u), src + i * 4);
            asm volatile("cp.async.commit_group;" ::: "memory");
        }

        #pragma unroll
        for (int i = 0; i < DD/2; i++) Zp[i] = b2u[i];

        // two hidden units per iteration (j, j+64); W1 via smem, W2 via const
        #pragma unroll 2
        for (int jj = 0; jj < HH / 2; jj++) {
            const int j0 = jj, j1 = jj + HH / 2;
            const ulonglong2* w1a = (const ulonglong2*)(W1T + j0 * DD);
            const ulonglong2* w1b = (const ulonglong2*)(W1T + j1 * DD);

            u64 a0 = zero2, a1 = zero2, c0v = zero2, c1v = zero2;
            #pragma unroll
            for (int i = 0; i < 8; i++) {
                ulonglong2 wa = w1a[i];
                ulonglong2 wb = w1b[i];
                a0  = fma2(Xp[2*i],   wa.x, a0);
                a1  = fma2(Xp[2*i+1], wa.y, a1);
                c0v = fma2(Xp[2*i],   wb.x, c0v);
                c1v = fma2(Xp[2*i+1], wb.y, c1v);
            }
            a0  = add2(a0, a1);
            c0v = add2(c0v, c1v);

            const float2 cc0 = cb[j0];
            const float2 cc1 = cb[j1];
            const float cs0 = fmaf(s, cc0.y, cc0.x);
            const float cs1 = fmaf(s, cc1.y, cc1.x);

            float t0, t1;
            unpack2(a0, t0, t1);  const float pre0 = cs0 + (t0 + t1);
            unpack2(c0v, t0, t1); const float pre1 = cs1 + (t0 + t1);

            const float h0 = ftanh(pre0);
            const float h1 = ftanh(pre1);
            const u64 h0p = pack2(h0, h0);
            const u64 h1p = pack2(h1, h1);

            // layer 2 weights from __constant__ (uniform index -> const port)
            const ulonglong2* w2a = (const ulonglong2*)(W2c + j0 * DD);
            const ulonglong2* w2b = (const ulonglong2*)(W2c + j1 * DD);
            #pragma unroll
            for (int i = 0; i < 8; i++) {
                ulonglong2 wa = w2a[i];
                ulonglong2 wb = w2b[i];
                Zp[2*i]   = fma2(h0p, wa.x, Zp[2*i]);
                Zp[2*i+1] = fma2(h0p, wa.y, Zp[2*i+1]);
                Zp[2*i]   = fma2(h1p, wb.x, Zp[2*i]);
                Zp[2*i+1] = fma2(h1p, wb.y, Zp[2*i+1]);
            }
        }

        // ---- epilogue (noise from shared) ----
        asm volatile("cp.async.wait_group 0;" ::: "memory");

        u64 s20 = zero2, s21 = zero2, s22 = zero2, s23 = zero2;
        u64 zw0 = zero2, zw1 = zero2, zw2 = zero2, zw3 = zero2;
        #pragma unroll
        for (int i = 0; i < 4; i++) {
            ulonglong2 nv0 = *(const ulonglong2*)(nrd + (2*i)     * (TPB * 4));
            ulonglong2 nv1 = *(const ulonglong2*)(nrd + (2*i + 1) * (TPB * 4));
            u64 za = Zp[4*i],     zb = Zp[4*i + 1];
            u64 zc = Zp[4*i + 2], zd = Zp[4*i + 3];
            s20 = fma2(za, za, s20);
            s21 = fma2(zb, zb, s21);
            s22 = fma2(zc, zc, s22);
            s23 = fma2(zd, zd, s23);
            u64 wa = mul2(sq2, nv0.x);
            u64 wb = mul2(sq2, nv0.y);
            u64 wc = mul2(sq2, nv1.x);
            u64 wd = mul2(sq2, nv1.y);
            zw0 = fma2(za, wa, zw0);
            zw1 = fma2(zb, wb, zw1);
            zw2 = fma2(zc, wc, zw2);
            zw3 = fma2(zd, wd, zw3);
            u64 d0 = fma2(ncr2, za, mul2(nth2, Xp[4*i]));
            u64 d1 = fma2(ncr2, zb, mul2(nth2, Xp[4*i + 1]));
            u64 d2 = fma2(ncr2, zc, mul2(nth2, Xp[4*i + 2]));
            u64 d3 = fma2(ncr2, zd, mul2(nth2, Xp[4*i + 3]));
            Xp[4*i]     = add2(fma2(dt2, d0, Xp[4*i]),     wa);
            Xp[4*i + 1] = add2(fma2(dt2, d1, Xp[4*i + 1]), wb);
            Xp[4*i + 2] = add2(fma2(dt2, d2, Xp[4*i + 2]), wc);
            Xp[4*i + 3] = add2(fma2(dt2, d3, Xp[4*i + 3]), wd);
        }
        s20 = add2(add2(s20, s21), add2(s22, s23));
        zw0 = add2(add2(zw0, zw1), add2(zw2, zw3));
        float qlo, qhi, wlo, whi;
        unpack2(s20, qlo, qhi);
        unpack2(zw0, wlo, whi);
        V = fmaf(dt * (0.5f - crf), qlo + qhi, V) + (wlo + whi);
    }

    // ---- store ----
    {
        ulonglong2* xo = (ulonglong2*)(outX + (size_t)p * DD);
        #pragma unroll
        for (int i = 0; i < DD/4; i++) {
            ulonglong2 v; v.x = Xp[2*i]; v.y = Xp[2*i+1];
            xo[i] = v;
        }
        outV[p] = V;
    }
}

extern "C" void kernel_launch(void* const* d_in, const int* in_sizes, int n_in,
                              void* d_out, int out_size) {
    const float* obs    = (const float*)d_in[0];
    const float* X0     = (const float*)d_in[1];
    const float* V0     = (const float*)d_in[2];
    const float* noise  = (const float*)d_in[3];
    const float* W1     = (const float*)d_in[4];
    const float* b1     = (const float*)d_in[5];
    const float* W2     = (const float*)d_in[6];
    const float* b2     = (const float*)d_in[7];
    const float* theta  = (const float*)d_in[8];
    const int*   obsidx = (const int*)d_in[9];
    const int*   cr     = (const int*)d_in[10];

    float* out  = (float*)d_out;
    float* outX = out;
    float* outV = out + (size_t)NPART * DD;

    // Stage W2 into constant memory (D2D async copy: graph-capturable, no alloc)
    cudaMemcpyToSymbolAsync(W2c, W2, HH * DD * sizeof(float), 0,
                            cudaMemcpyDeviceToDevice, 0);

    cudaFuncSetAttribute(sde_kernel,
                         cudaFuncAttributeMaxDynamicSharedMemorySize, SMEM_BYTES);
    sde_kernel<<<NBLK, TPB, SMEM_BYTES>>>(obs, X0, V0, noise, W1, b1, b2,
                                          theta, obsidx, cr, outX, outV);
}

// round 13
// speedup vs baseline: 1.1551x; 1.0278x over previous
#include <cuda_runtime.h>
#include <math.h>
#include <cstdint>

#define NPART 32768
#define DD 32
#define PP 8
#define HH 128
#define MS 50
#define TPB 256
#define NBLK 128   // TPB*NBLK == NPART exactly

typedef unsigned long long u64;

// W2 weights, j-major [128][32] — read over the constant port.
__constant__ float W2c[HH * DD];

// ---- packed f32x2 helpers (sm_103a) ----
__device__ __forceinline__ u64 pack2(float lo, float hi) {
    u64 r; asm("mov.b64 %0, {%1, %2};" : "=l"(r) : "f"(lo), "f"(hi)); return r;
}
__device__ __forceinline__ void unpack2(u64 v, float& lo, float& hi) {
    asm("mov.b64 {%0, %1}, %2;" : "=f"(lo), "=f"(hi) : "l"(v));
}
__device__ __forceinline__ u64 fma2(u64 a, u64 b, u64 c) {
    u64 d; asm("fma.rn.f32x2 %0, %1, %2, %3;" : "=l"(d) : "l"(a), "l"(b), "l"(c)); return d;
}
__device__ __forceinline__ u64 add2(u64 a, u64 b) {
    u64 d; asm("add.rn.f32x2 %0, %1, %2;" : "=l"(d) : "l"(a), "l"(b)); return d;
}
__device__ __forceinline__ u64 mul2(u64 a, u64 b) {
    u64 d; asm("mul.rn.f32x2 %0, %1, %2;" : "=l"(d) : "l"(a), "l"(b)); return d;
}
__device__ __forceinline__ uint32_t smem_u32(const void* p) {
    uint32_t a;
    asm("{ .reg .u64 t; cvta.to.shared.u64 t, %1; cvt.u32.u64 %0, t; }"
        : "=r"(a) : "l"(p));
    return a;
}
__device__ __forceinline__ float ftanh(float a) {
    float e = __expf(2.0f * a);
    return 1.0f - __fdividef(2.0f, e + 1.0f);
}
#define CP16(dst, src) \
    asm volatile("cp.async.cg.shared.global [%0], [%1], 16;" \
                 :: "r"(dst), "l"(src) : "memory")

// dynamic shared layout (float offsets)
#define F_W1T 0                      // [j][i] 128x32
#define F_NS  (F_W1T + HH * DD)      // noise staging: [chunk(8)][tid(256)][4]
#define SMEM_FLOATS (F_NS + TPB * DD)
#define SMEM_BYTES (SMEM_FLOATS * 4)

// layer-1 for hidden units (JJ, JJ+64): 16 fma2 + 2 add2, one LDS.64 for cs pair
#define LAYER1(JJ, CSP, P0, P1) do { \
    const ulonglong2* _w1a = (const ulonglong2*)(W1T + (JJ) * DD); \
    const ulonglong2* _w1b = (const ulonglong2*)(W1T + ((JJ) + 64) * DD); \
    u64 _q0 = zero2, _q1 = zero2, _q2 = zero2, _q3 = zero2; \
    _Pragma("unroll") \
    for (int _i = 0; _i < 8; _i++) { \
        ulonglong2 _wa = _w1a[_i]; \
        ulonglong2 _wb = _w1b[_i]; \
        _q0 = fma2(Xp[2*_i],   _wa.x, _q0); \
        _q1 = fma2(Xp[2*_i+1], _wa.y, _q1); \
        _q2 = fma2(Xp[2*_i],   _wb.x, _q2); \
        _q3 = fma2(Xp[2*_i+1], _wb.y, _q3); \
    } \
    _q0 = add2(_q0, _q1); \
    _q2 = add2(_q2, _q3); \
    const float2 _cs = (CSP)[JJ]; \
    float _tl, _th; \
    unpack2(_q0, _tl, _th); (P0) = _cs.x + (_tl + _th); \
    unpack2(_q2, _tl, _th); (P1) = _cs.y + (_tl + _th); \
} while (0)

// layer-2 accumulate for hidden units (JJ, JJ+64): 32 fma2, W2 via const port
#define LAYER2(JJ, H0P, H1P) do { \
    const ulonglong2* _w2a = (const ulonglong2*)(W2c + (JJ) * DD); \
    const ulonglong2* _w2b = (const ulonglong2*)(W2c + ((JJ) + 64) * DD); \
    _Pragma("unroll") \
    for (int _i = 0; _i < 8; _i++) { \
        ulonglong2 _wa = _w2a[_i]; \
        ulonglong2 _wb = _w2b[_i]; \
        Zp[2*_i]   = fma2((H0P), _wa.x, Zp[2*_i]); \
        Zp[2*_i+1] = fma2((H0P), _wa.y, Zp[2*_i+1]); \
        Zp[2*_i]   = fma2((H1P), _wb.x, Zp[2*_i]); \
        Zp[2*_i+1] = fma2((H1P), _wb.y, Zp[2*_i+1]); \
    } \
} while (0)

__global__ __launch_bounds__(TPB, 1)
void sde_kernel(const float* __restrict__ obs,
                const float* __restrict__ X0,
                const float* __restrict__ V0,
                const float* __restrict__ noise,
                const float* __restrict__ W1,
                const float* __restrict__ b1,
                const float* __restrict__ b2,
                const float* __restrict__ theta_p,
                const int*   __restrict__ obsidx_p,
                const int*   __restrict__ cr_p,
                float* __restrict__ outX,
                float* __restrict__ outV)
{
    extern __shared__ __align__(16) float sm[];
    float* W1T = sm + F_W1T;
    float* ns  = sm + F_NS;

    __shared__ float2 cb[HH];           // (base_j, w40_j)
    __shared__ float2 cspbuf[2][HH/2];  // per-step cs pairs, double-buffered
    __shared__ __align__(16) float b2s[DD];

    const int tid = threadIdx.x;

    // ---- stage W1^T + folded constants ----
    for (int idx = tid; idx < DD * HH; idx += TPB) {
        int i = idx >> 7;            // feature
        int j = idx & (HH - 1);      // hidden unit
        W1T[j * DD + i] = W1[idx];
    }
    if (tid < DD) b2s[tid] = b2[tid];
    if (tid < HH) {
        const int j = tid;
        float base = b1[j];
        #pragma unroll
        for (int q = 0; q < PP; q++)
            base = fmaf(obs[q], W1[(DD + q) * HH + j], base);
        base = fmaf((float)(*obsidx_p), W1[41 * HH + j], base);
        cb[j] = make_float2(base, W1[40 * HH + j]);
    }

    const float theta = *theta_p;
    const float crf   = (float)(*cr_p);
    const float dt    = 0.02f;
    const float sqdt  = sqrtf(dt);

    const u64 sq2   = pack2(sqdt, sqdt);
    const u64 dt2   = pack2(dt, dt);
    const u64 nth2  = pack2(-theta, -theta);
    const u64 ncr2  = pack2(-crf, -crf);
    const u64 zero2 = pack2(0.f, 0.f);

    const int p = (int)blockIdx.x * TPB + tid;   // exactly NPART threads

    const uint32_t nsu = smem_u32(ns) + (uint32_t)tid * 16u;
    const float* nrd = ns + tid * 4;

    __syncthreads();

    // ---- state packed f32x2: X 16 u64, Z 16 u64 ----
    u64 Xp[DD/2], Zp[DD/2];
    {
        const ulonglong2* xr = (const ulonglong2*)(X0 + (size_t)p * DD);
        #pragma unroll
        for (int i = 0; i < DD/4; i++) {
            ulonglong2 v = xr[i];
            Xp[2*i] = v.x; Xp[2*i+1] = v.y;
        }
    }
    float V = V0[p];

    const u64* b2u = (const u64*)b2s;

    for (int m = 0; m < MS; m++) {
        const float s = (float)m * dt;
        const float2* csp = cspbuf[m & 1];

        // per-step cs pairs (one thread per jj), double-buffered
        if (tid < HH / 2) {
            float2 ca = cb[tid];
            float2 cbx = cb[tid + HH / 2];
            cspbuf[m & 1][tid] =
                make_float2(fmaf(s, ca.y, ca.x), fmaf(s, cbx.y, cbx.x));
        }

        // stage this step's noise row into shared (epilogue consumes)
        {
            const float* src = noise + ((size_t)m * NPART + p) * DD;
            #pragma unroll
            for (int i = 0; i < 8; i++)
                CP16(nsu + (uint32_t)i * (TPB * 16u), src + i * 4);
            asm volatile("cp.async.commit_group;" ::: "memory");
        }
        __syncthreads();   // csp ready (also orders double-buffer reuse)

        #pragma unroll
        for (int i = 0; i < DD/2; i++) Zp[i] = b2u[i];

        // ---- software-pipelined MLP: tanh(jj) hides under layer1(jj+1) ----
        float pre0, pre1;
        LAYER1(0, csp, pre0, pre1);
        #pragma unroll 2
        for (int jj = 0; jj < HH / 2 - 1; jj++) {
            const float h0 = ftanh(pre0);     // MUFU chain issued...
            const float h1 = ftanh(pre1);
            float npre0, npre1;
            LAYER1(jj + 1, csp, npre0, npre1); // ...overlapped with this
            const u64 h0p = pack2(h0, h0);
            const u64 h1p = pack2(h1, h1);
            LAYER2(jj, h0p, h1p);
            pre0 = npre0;
            pre1 = npre1;
        }
        {
            const float h0 = ftanh(pre0);
            const float h1 = ftanh(pre1);
            const u64 h0p = pack2(h0, h0);
            const u64 h1p = pack2(h1, h1);
            LAYER2(HH / 2 - 1, h0p, h1p);
        }

        // ---- epilogue (noise from shared) ----
        asm volatile("cp.async.wait_group 0;" ::: "memory");

        u64 s20 = zero2, s21 = zero2, s22 = zero2, s23 = zero2;
        u64 zw0 = zero2, zw1 = zero2, zw2 = zero2, zw3 = zero2;
        #pragma unroll
        for (int i = 0; i < 4; i++) {
            ulonglong2 nv0 = *(const ulonglong2*)(nrd + (2*i)     * (TPB * 4));
            ulonglong2 nv1 = *(const ulonglong2*)(nrd + (2*i + 1) * (TPB * 4));
            u64 za = Zp[4*i],     zb = Zp[4*i + 1];
            u64 zc = Zp[4*i + 2], zd = Zp[4*i + 3];
            s20 = fma2(za, za, s20);
            s21 = fma2(zb, zb, s21);
            s22 = fma2(zc, zc, s22);
            s23 = fma2(zd, zd, s23);
            u64 wa = mul2(sq2, nv0.x);
            u64 wb = mul2(sq2, nv0.y);
            u64 wc = mul2(sq2, nv1.x);
            u64 wd = mul2(sq2, nv1.y);
            zw0 = fma2(za, wa, zw0);
            zw1 = fma2(zb, wb, zw1);
            zw2 = fma2(zc, wc, zw2);
            zw3 = fma2(zd, wd, zw3);
            u64 d0 = fma2(ncr2, za, mul2(nth2, Xp[4*i]));
            u64 d1 = fma2(ncr2, zb, mul2(nth2, Xp[4*i + 1]));
            u64 d2 = fma2(ncr2, zc, mul2(nth2, Xp[4*i + 2]));
            u64 d3 = fma2(ncr2, zd, mul2(nth2, Xp[4*i + 3]));
            Xp[4*i]     = add2(fma2(dt2, d0, Xp[4*i]),     wa);
            Xp[4*i + 1] = add2(fma2(dt2, d1, Xp[4*i + 1]), wb);
            Xp[4*i + 2] = add2(fma2(dt2, d2, Xp[4*i + 2]), wc);
            Xp[4*i + 3] = add2(fma2(dt2, d3, Xp[4*i + 3]), wd);
        }
        s20 = add2(add2(s20, s21), add2(s22, s23));
        zw0 = add2(add2(zw0, zw1), add2(zw2, zw3));
        float qlo, qhi, wlo, whi;
        unpack2(s20, qlo, qhi);
        unpack2(zw0, wlo, whi);
        V = fmaf(dt * (0.5f - crf), qlo + qhi, V) + (wlo + whi);
    }

    // ---- store ----
    {
        ulonglong2* xo = (ulonglong2*)(outX + (size_t)p * DD);
        #pragma unroll
        for (int i = 0; i < DD/4; i++) {
            ulonglong2 v; v.x = Xp[2*i]; v.y = Xp[2*i+1];
            xo[i] = v;
        }
        outV[p] = V;
    }
}

extern "C" void kernel_launch(void* const* d_in, const int* in_sizes, int n_in,
                              void* d_out, int out_size) {
    const float* obs    = (const float*)d_in[0];
    const float* X0     = (const float*)d_in[1];
    const float* V0     = (const float*)d_in[2];
    const float* noise  = (const float*)d_in[3];
    const float* W1     = (const float*)d_in[4];
    const float* b1     = (const float*)d_in[5];
    const float* W2     = (const float*)d_in[6];
    const float* b2     = (const float*)d_in[7];
    const float* theta  = (const float*)d_in[8];
    const int*   obsidx = (const int*)d_in[9];
    const int*   cr     = (const int*)d_in[10];

    float* out  = (float*)d_out;
    float* outX = out;
    float* outV = out + (size_t)NPART * DD;

    // Stage W2 into constant memory (D2D async copy: graph-capturable, no alloc)
    cudaMemcpyToSymbolAsync(W2c, W2, HH * DD * sizeof(float), 0,
                            cudaMemcpyDeviceToDevice, 0);

    cudaFuncSetAttribute(sde_kernel,
                         cudaFuncAttributeMaxDynamicSharedMemorySize, SMEM_BYTES);
    sde_kernel<<<NBLK, TPB, SMEM_BYTES>>>(obs, X0, V0, noise, W1, b1, b2,
                                          theta, obsidx, cr, outX, outV);
}